// round 7
// baseline (speedup 1.0000x reference)
#include <cuda_runtime.h>
#include <cuda_fp16.h>

#define N_NODES 50000
#define N_EDGES 800000
#define HEADS 3
#define HC 192
#define NEG_SLOPE 0.2f
#define NTILES 49   // ceil(50000/1024)

// ---------------- scratch ------------------------------------------------------
__device__ __half  g_xh[N_NODES * HC];       // x @ W_node (fp16, message path)
__device__ float   g_sn[N_NODES * 8];        // [0..2]=s0(h), [4..6]=s2(h)
__device__ float   g_q[64];                  // folded edge-att vector (48 used)
__device__ float   g_v[6 * 64];              // folded node-att vectors v0/v2
__device__ float4  g_wsrc[N_EDGES];          // CSR: (w0,w1,w2, src-bits)
__device__ int     g_eid[N_EDGES];           // CSR: original edge id
__device__ int     g_deg[N_NODES];
__device__ int     g_rowptr[N_NODES + 1];
__device__ int     g_cursor[N_NODES];
__device__ int     g_tsum[64], g_toff[64];
__device__ float   g_aggr[N_NODES * HC];

// ---------------- f32x2 helpers -------------------------------------------------
__device__ __forceinline__ unsigned long long pk2(float lo, float hi) {
    unsigned long long r;
    asm("mov.b64 %0, {%1,%2};" : "=l"(r) : "f"(lo), "f"(hi));
    return r;
}
__device__ __forceinline__ void fma2(unsigned long long& d,
                                     unsigned long long a,
                                     unsigned long long b) {
    asm("fma.rn.f32x2 %0, %1, %2, %0;" : "+l"(d) : "l"(a), "l"(b));
}
__device__ __forceinline__ void unpk2(float& lo, float& hi, unsigned long long v) {
    asm("mov.b64 {%0,%1}, %2;" : "=f"(lo), "=f"(hi) : "l"(v));
}
__device__ __forceinline__ float hsum2(unsigned long long v) {
    float lo, hi; unpk2(lo, hi, v); return lo + hi;
}

// ---------------- K: zero degree histogram --------------------------------------
__global__ void k_zero() {
    int i = blockIdx.x * blockDim.x + threadIdx.x;
    if (i < N_NODES) g_deg[i] = 0;
}

// ---------------- K: degree histogram -------------------------------------------
__global__ void k_deg(const int* __restrict__ ei) {
    int e = blockIdx.x * blockDim.x + threadIdx.x;
    if (e < N_EDGES) atomicAdd(&g_deg[ei[N_EDGES + e]], 1);
}

// ---------------- K: fold attention vectors -------------------------------------
// q[h,k]   = sum_c We[k, h*64+c] * att[h,1,c]           (48 outputs)
// v[o,k]   = sum_c Wn[k, h*64+c] * att[h,type?2:0,c]    (o = type*3+h, 384 outs)
__global__ void k_fold(const float* __restrict__ Wn, const float* __restrict__ We,
                       const float* __restrict__ att) {
    int t = threadIdx.x;
    if (t < 48) {
        int h = t >> 4, k = t & 15;
        float s = 0.f;
        const float* wr = We + k * HC + h * 64;
        const float* ar = att + h * HC + 64;
#pragma unroll 8
        for (int c = 0; c < 64; c++) s += wr[c] * ar[c];
        g_q[t] = s;
    } else if (t < 48 + 384) {
        int o2 = t - 48;
        int o = o2 >> 6, k = o2 & 63;
        int type = (o >= 3), h = (o >= 3) ? o - 3 : o;
        float s = 0.f;
        const float* wr = Wn + k * HC + h * 64;
        const float* ar = att + h * HC + type * 128;
#pragma unroll 8
        for (int c = 0; c < 64; c++) s += wr[c] * ar[c];
        g_v[o * 64 + k] = s;
    }
}

// ---------------- K: x_proj = x @ W_node (fp16 out) + shuffle-free s0/s2 --------
// 96 threads; thread t owns channels (t, t+96), 8 nodes per block.
__global__ void k_projs(const float* __restrict__ x, const float* __restrict__ Wn) {
    __shared__ __align__(16) float xT[64 * 8];  // [k][n]
    __shared__ float s_v[6 * 65];               // padded folded vectors
    int n0 = blockIdx.x * 8;
    int t = threadIdx.x;                 // 0..95
    int ch0 = t, ch1 = t + 96;
    for (int i = t; i < 8 * 64; i += 96) {
        int n = i >> 6, k = i & 63;
        xT[k * 8 + n] = x[(n0 + n) * 64 + k];
    }
    for (int i = t; i < 384; i += 96) {
        int o = i >> 6, k = i & 63;
        s_v[o * 65 + k] = g_v[i];
    }
    __syncthreads();
    unsigned long long accA2[4], accB2[4];
#pragma unroll
    for (int p = 0; p < 4; p++) { accA2[p] = 0ull; accB2[p] = 0ull; }
#pragma unroll 4
    for (int k = 0; k < 64; k++) {
        float wa = Wn[k * HC + ch0];
        float wb = Wn[k * HC + ch1];
        unsigned long long wa2 = pk2(wa, wa), wb2 = pk2(wb, wb);
        const ulonglong2* xr = reinterpret_cast<const ulonglong2*>(xT + k * 8);
        ulonglong2 x01 = xr[0], x23 = xr[1];
        fma2(accA2[0], x01.x, wa2); fma2(accA2[1], x01.y, wa2);
        fma2(accA2[2], x23.x, wa2); fma2(accA2[3], x23.y, wa2);
        fma2(accB2[0], x01.x, wb2); fma2(accB2[1], x01.y, wb2);
        fma2(accB2[2], x23.x, wb2); fma2(accB2[3], x23.y, wb2);
    }
    float accA[8], accB[8];
#pragma unroll
    for (int p = 0; p < 4; p++) {
        unpk2(accA[2 * p], accA[2 * p + 1], accA2[p]);
        unpk2(accB[2 * p], accB[2 * p + 1], accB2[p]);
    }
#pragma unroll
    for (int n = 0; n < 8; n++) {
        g_xh[(n0 + n) * HC + ch0] = __float2half(accA[n]);
        g_xh[(n0 + n) * HC + ch1] = __float2half(accB[n]);
    }

    // shuffle-free s0/s2: 48 dots of length 64 from the staged xT tile
    if (t < 48) {
        int n = t & 7, o = t >> 3;          // o = type*3 + h
        int type = (o >= 3), h = (o >= 3) ? o - 3 : o;
        const float* vv = s_v + o * 65;
        float s = 0.f;
#pragma unroll 8
        for (int k = 0; k < 64; k++) s += xT[k * 8 + n] * vv[k];
        g_sn[(n0 + n) * 8 + type * 4 + h] = s;
    }
}

// ---------------- K: scan phase 1 — per-tile exclusive scans + tile totals ------
__global__ void k_scan1() {
    __shared__ int s_ws[32], s_off[32];
    int t = threadIdx.x, w = t >> 5, lane = t & 31;
    int i = blockIdx.x * 1024 + t;
    int v = (i < N_NODES) ? g_deg[i] : 0;
    int incl = v;
#pragma unroll
    for (int o = 1; o < 32; o <<= 1) {
        int u = __shfl_up_sync(0xffffffffu, incl, o);
        if (lane >= o) incl += u;
    }
    if (lane == 31) s_ws[w] = incl;
    __syncthreads();
    if (w == 0) {
        int wv = s_ws[lane];
        int inc2 = wv;
#pragma unroll
        for (int o = 1; o < 32; o <<= 1) {
            int u = __shfl_up_sync(0xffffffffu, inc2, o);
            if (lane >= o) inc2 += u;
        }
        s_off[lane] = inc2 - wv;
        if (lane == 31) g_tsum[blockIdx.x] = inc2;
    }
    __syncthreads();
    if (i < N_NODES) g_rowptr[i] = s_off[w] + incl - v;  // tile-local exclusive
}

// ---------------- K: scan phase 2 — scan tile totals (1 block, 64 thr) ----------
__global__ void k_scan2() {
    __shared__ int s[64];
    int t = threadIdx.x;
    int v = (t < NTILES) ? g_tsum[t] : 0;
    s[t] = v;
    __syncthreads();
#pragma unroll
    for (int o = 1; o < 64; o <<= 1) {
        int add = (t >= o) ? s[t - o] : 0;
        __syncthreads();
        s[t] += add;
        __syncthreads();
    }
    if (t < NTILES) g_toff[t] = s[t] - v;
    if (t == NTILES - 1) g_rowptr[N_NODES] = s[t];
}

// ---------------- K: scan phase 3 — add tile offsets, init cursor ---------------
__global__ void k_scan3() {
    int i = blockIdx.x * 1024 + threadIdx.x;
    if (i < N_NODES) {
        int v = g_rowptr[i] + g_toff[blockIdx.x];
        g_rowptr[i] = v;
        g_cursor[i] = v;
    }
}

// ---------------- K: exp(leaky(alpha)) + light CSR scatter -----------------------
__global__ void k_alpha(const int* __restrict__ ei,
                        const float* __restrict__ eattr) {
    __shared__ float qs[48];
    if (threadIdx.x < 48) qs[threadIdx.x] = g_q[threadIdx.x];
    __syncthreads();
    int e = blockIdx.x * blockDim.x + threadIdx.x;
    if (e >= N_EDGES) return;
    int src = ei[e];
    int dst = ei[N_EDGES + e];
    const float4* ap = reinterpret_cast<const float4*>(eattr) + (size_t)e * 4;
    float4 a0 = ap[0], a1 = ap[1], a2 = ap[2], a3 = ap[3];
    float4 sd = *reinterpret_cast<const float4*>(g_sn + (size_t)dst * 8);
    float4 ss = *reinterpret_cast<const float4*>(g_sn + (size_t)src * 8 + 4);
    float base3[3] = {sd.x + ss.x, sd.y + ss.y, sd.z + ss.z};
    float w[3];
#pragma unroll
    for (int h = 0; h < 3; h++) {
        const float* q = qs + h * 16;
        float s = base3[h];
        s += a0.x * q[0]  + a0.y * q[1]  + a0.z * q[2]  + a0.w * q[3];
        s += a1.x * q[4]  + a1.y * q[5]  + a1.z * q[6]  + a1.w * q[7];
        s += a2.x * q[8]  + a2.y * q[9]  + a2.z * q[10] + a2.w * q[11];
        s += a3.x * q[12] + a3.y * q[13] + a3.z * q[14] + a3.w * q[15];
        s = (s >= 0.f) ? s : NEG_SLOPE * s;   // leaky relu
        w[h] = __expf(s);                     // shift-free softmax numerator
    }
    int pos = atomicAdd(&g_cursor[dst], 1);
    g_wsrc[pos] = make_float4(w[0], w[1], w[2], __int_as_float(src));
    g_eid[pos] = e;
}

// ---------------- K: per-node aggregation ----------------------------------------
// 96 threads: thread t owns channels (2t, 2t+1); head h = t>>5 (warp-uniform).
#define CHUNK 32
__global__ void k_aggr(const float* __restrict__ eattr,
                       const float* __restrict__ We) {
    int t = threadIdx.x;
    int c0 = 2 * t;
    int h = t >> 5;

    unsigned long long Wp0[8], Wp1[8];
#pragma unroll
    for (int m = 0; m < 8; m++) {
        Wp0[m] = pk2(We[(2 * m) * HC + c0],     We[(2 * m + 1) * HC + c0]);
        Wp1[m] = pk2(We[(2 * m) * HC + c0 + 1], We[(2 * m + 1) * HC + c0 + 1]);
    }

    __shared__ float s_w[3 * CHUNK];
    __shared__ int   s_src[CHUNK];
    __shared__ __align__(16) float s_ea[CHUNK * 16];

    for (int i = blockIdx.x; i < N_NODES; i += gridDim.x) {
        int rs = g_rowptr[i], re = g_rowptr[i + 1];
        float z = 0.f;
        unsigned long long acc0 = 0ull, acc1 = 0ull;

        for (int base = rs; base < re; base += CHUNK) {
            int Cn = min(CHUNK, re - base);
            if (t < Cn) {
                float4 ws = g_wsrc[base + t];
                s_w[0 * CHUNK + t] = ws.x;
                s_w[1 * CHUNK + t] = ws.y;
                s_w[2 * CHUNK + t] = ws.z;
                s_src[t] = __float_as_int(ws.w);
                int eid = g_eid[base + t];
                const float4* ap =
                    reinterpret_cast<const float4*>(eattr) + (size_t)eid * 4;
                float4 b0 = ap[0], b1 = ap[1], b2 = ap[2], b3 = ap[3];
                float4* sp = reinterpret_cast<float4*>(s_ea + t * 16);
                sp[0] = b0; sp[1] = b1; sp[2] = b2; sp[3] = b3;
            }
            __syncthreads();

            int srcc = s_src[0];
            __half2 xh = *reinterpret_cast<const __half2*>(
                g_xh + (size_t)srcc * HC + c0);
            for (int j = 0; j < Cn; j++) {
                __half2 xhn;
                if (j + 1 < Cn) {
                    int srcn = s_src[j + 1];
                    xhn = *reinterpret_cast<const __half2*>(
                        g_xh + (size_t)srcn * HC + c0);
                }
                float2 xj = __half22float2(xh);
                const ulonglong2* eap =
                    reinterpret_cast<const ulonglong2*>(s_ea + j * 16);
                ulonglong2 p0 = eap[0], p1 = eap[1], p2 = eap[2], p3 = eap[3];
                unsigned long long e0 = 0ull, e1 = 0ull;
                fma2(e0, p0.x, Wp0[0]); fma2(e1, p0.x, Wp1[0]);
                fma2(e0, p0.y, Wp0[1]); fma2(e1, p0.y, Wp1[1]);
                fma2(e0, p1.x, Wp0[2]); fma2(e1, p1.x, Wp1[2]);
                fma2(e0, p1.y, Wp0[3]); fma2(e1, p1.y, Wp1[3]);
                fma2(e0, p2.x, Wp0[4]); fma2(e1, p2.x, Wp1[4]);
                fma2(e0, p2.y, Wp0[5]); fma2(e1, p2.y, Wp1[5]);
                fma2(e0, p3.x, Wp0[6]); fma2(e1, p3.x, Wp1[6]);
                fma2(e0, p3.y, Wp0[7]); fma2(e1, p3.y, Wp1[7]);
                float w = s_w[h * CHUNK + j];
                z += w;
                float wx0 = w * xj.x, wx1 = w * xj.y;
                fma2(acc0, e0, pk2(wx0, wx0));
                fma2(acc1, e1, pk2(wx1, wx1));
                xh = xhn;
            }
            __syncthreads();
        }
        float inv = 1.f / (z + 1e-16f);
        *reinterpret_cast<float2*>(g_aggr + (size_t)i * HC + c0) =
            make_float2(hsum2(acc0) * inv, hsum2(acc1) * inv);
    }
}

// ---------------- K: out = aggr @ W_scale + bias ---------------------------------
__global__ void k_out(const float* __restrict__ Ws, const float* __restrict__ bias,
                      float* __restrict__ out) {
    __shared__ __align__(16) float aT[HC * 8];  // [k][n]
    int n0 = blockIdx.x * 8;
    int t = threadIdx.x;  // 0..63
    for (int i = t; i < 8 * HC; i += 64) {
        int n = i / HC, k = i - n * HC;
        aT[k * 8 + n] = g_aggr[(n0 + n) * HC + k];
    }
    __syncthreads();
    unsigned long long acc2[4];
#pragma unroll
    for (int p = 0; p < 4; p++) acc2[p] = 0ull;
#pragma unroll 4
    for (int k = 0; k < HC; k++) {
        unsigned long long wv2 = pk2(Ws[k * 64 + t], Ws[k * 64 + t]);
        const ulonglong2* ar =
            reinterpret_cast<const ulonglong2*>(aT + k * 8);
        ulonglong2 v01 = ar[0], v23 = ar[1];
        fma2(acc2[0], v01.x, wv2); fma2(acc2[1], v01.y, wv2);
        fma2(acc2[2], v23.x, wv2); fma2(acc2[3], v23.y, wv2);
    }
    float acc[8];
#pragma unroll
    for (int p = 0; p < 4; p++) unpk2(acc[2 * p], acc[2 * p + 1], acc2[p]);
    float b = bias[t];
#pragma unroll
    for (int n = 0; n < 8; n++) out[(n0 + n) * 64 + t] = acc[n] + b;
}

// ---------------- launch ----------------------------------------------------------
extern "C" void kernel_launch(void* const* d_in, const int* in_sizes, int n_in,
                              void* d_out, int out_size) {
    const float* x     = (const float*)d_in[0];
    const int*   ei    = (const int*)d_in[1];
    const float* eattr = (const float*)d_in[2];
    const float* Wn    = (const float*)d_in[3];
    const float* We    = (const float*)d_in[4];
    const float* att   = (const float*)d_in[5];
    const float* Ws    = (const float*)d_in[6];
    const float* bias  = (const float*)d_in[7];
    float*       out   = (float*)d_out;

    k_zero<<<(N_NODES + 255) / 256, 256>>>();
    k_deg<<<(N_EDGES + 255) / 256, 256>>>(ei);
    k_fold<<<1, 448>>>(Wn, We, att);
    k_projs<<<N_NODES / 8, 96>>>(x, Wn);
    k_scan1<<<NTILES, 1024>>>();
    k_scan2<<<1, 64>>>();
    k_scan3<<<NTILES, 1024>>>();
    k_alpha<<<(N_EDGES + 255) / 256, 256>>>(ei, eattr);
    k_aggr<<<3072, 96>>>(eattr, We);
    k_out<<<N_NODES / 8, 64>>>(Ws, bias, out);
}

// round 8
// speedup vs baseline: 1.0565x; 1.0565x over previous
#include <cuda_runtime.h>
#include <cuda_fp16.h>

#define N_NODES 50000
#define N_EDGES 800000
#define HEADS 3
#define HC 192
#define NEG_SLOPE 0.2f
#define NTILES 49   // ceil(50000/1024)

// ---------------- scratch ------------------------------------------------------
__device__ __half  g_xh[N_NODES * HC];       // x @ W_node (fp16, message path)
__device__ float   g_sn[N_NODES * 8];        // [0..2]=s0(h), [4..6]=s2(h)
__device__ float   g_q[64];                  // folded edge-att vector (48 used)
__device__ float   g_v[6 * 64];              // folded node-att vectors v0/v2
__device__ float4  g_wsrc[N_EDGES];          // CSR: (w0,w1,w2, src-bits)
__device__ int     g_eid[N_EDGES];           // CSR: original edge id
__device__ int     g_deg[N_NODES];
__device__ int     g_rowptr[N_NODES + 1];
__device__ int     g_cursor[N_NODES];
__device__ int     g_tsum[64], g_toff[64];
__device__ float   g_aggr[N_NODES * HC];

// ---------------- f32x2 helpers -------------------------------------------------
__device__ __forceinline__ unsigned long long pk2(float lo, float hi) {
    unsigned long long r;
    asm("mov.b64 %0, {%1,%2};" : "=l"(r) : "f"(lo), "f"(hi));
    return r;
}
__device__ __forceinline__ void fma2(unsigned long long& d,
                                     unsigned long long a,
                                     unsigned long long b) {
    asm("fma.rn.f32x2 %0, %1, %2, %0;" : "+l"(d) : "l"(a), "l"(b));
}
__device__ __forceinline__ void unpk2(float& lo, float& hi, unsigned long long v) {
    asm("mov.b64 {%0,%1}, %2;" : "=f"(lo), "=f"(hi) : "l"(v));
}
__device__ __forceinline__ float hsum2(unsigned long long v) {
    float lo, hi; unpk2(lo, hi, v); return lo + hi;
}

// ---------------- K: zero degree histogram --------------------------------------
__global__ void k_zero() {
    int i = blockIdx.x * blockDim.x + threadIdx.x;
    if (i < N_NODES) g_deg[i] = 0;
}

// ---------------- K: degree histogram -------------------------------------------
__global__ void k_deg(const int* __restrict__ ei) {
    int e = blockIdx.x * blockDim.x + threadIdx.x;
    if (e < N_EDGES) atomicAdd(&g_deg[ei[N_EDGES + e]], 1);
}

// ---------------- K: fold attention vectors -------------------------------------
__global__ void k_fold(const float* __restrict__ Wn, const float* __restrict__ We,
                       const float* __restrict__ att) {
    int t = threadIdx.x;
    if (t < 48) {
        int h = t >> 4, k = t & 15;
        float s = 0.f;
        const float* wr = We + k * HC + h * 64;
        const float* ar = att + h * HC + 64;
#pragma unroll 8
        for (int c = 0; c < 64; c++) s += wr[c] * ar[c];
        g_q[t] = s;
    } else if (t < 48 + 384) {
        int o2 = t - 48;
        int o = o2 >> 6, k = o2 & 63;
        int type = (o >= 3), h = (o >= 3) ? o - 3 : o;
        float s = 0.f;
        const float* wr = Wn + k * HC + h * 64;
        const float* ar = att + h * HC + type * 128;
#pragma unroll 8
        for (int c = 0; c < 64; c++) s += wr[c] * ar[c];
        g_v[o * 64 + k] = s;
    }
}

// ---------------- K: x_proj = x @ W_node (fp16 out) + shuffle-free s0/s2 --------
__global__ void k_projs(const float* __restrict__ x, const float* __restrict__ Wn) {
    __shared__ __align__(16) float xT[64 * 8];  // [k][n]
    __shared__ float s_v[6 * 65];               // padded folded vectors
    int n0 = blockIdx.x * 8;
    int t = threadIdx.x;                 // 0..95
    int ch0 = t, ch1 = t + 96;
    for (int i = t; i < 8 * 64; i += 96) {
        int n = i >> 6, k = i & 63;
        xT[k * 8 + n] = x[(n0 + n) * 64 + k];
    }
    for (int i = t; i < 384; i += 96) {
        int o = i >> 6, k = i & 63;
        s_v[o * 65 + k] = g_v[i];
    }
    __syncthreads();
    unsigned long long accA2[4], accB2[4];
#pragma unroll
    for (int p = 0; p < 4; p++) { accA2[p] = 0ull; accB2[p] = 0ull; }
#pragma unroll 4
    for (int k = 0; k < 64; k++) {
        float wa = Wn[k * HC + ch0];
        float wb = Wn[k * HC + ch1];
        unsigned long long wa2 = pk2(wa, wa), wb2 = pk2(wb, wb);
        const ulonglong2* xr = reinterpret_cast<const ulonglong2*>(xT + k * 8);
        ulonglong2 x01 = xr[0], x23 = xr[1];
        fma2(accA2[0], x01.x, wa2); fma2(accA2[1], x01.y, wa2);
        fma2(accA2[2], x23.x, wa2); fma2(accA2[3], x23.y, wa2);
        fma2(accB2[0], x01.x, wb2); fma2(accB2[1], x01.y, wb2);
        fma2(accB2[2], x23.x, wb2); fma2(accB2[3], x23.y, wb2);
    }
    float accA[8], accB[8];
#pragma unroll
    for (int p = 0; p < 4; p++) {
        unpk2(accA[2 * p], accA[2 * p + 1], accA2[p]);
        unpk2(accB[2 * p], accB[2 * p + 1], accB2[p]);
    }
#pragma unroll
    for (int n = 0; n < 8; n++) {
        g_xh[(n0 + n) * HC + ch0] = __float2half(accA[n]);
        g_xh[(n0 + n) * HC + ch1] = __float2half(accB[n]);
    }

    // shuffle-free s0/s2: 48 dots of length 64 from the staged xT tile
    if (t < 48) {
        int n = t & 7, o = t >> 3;          // o = type*3 + h
        int type = (o >= 3), h = (o >= 3) ? o - 3 : o;
        const float* vv = s_v + o * 65;
        float s = 0.f;
#pragma unroll 8
        for (int k = 0; k < 64; k++) s += xT[k * 8 + n] * vv[k];
        g_sn[(n0 + n) * 8 + type * 4 + h] = s;
    }
}

// ---------------- K: scan phase 1 — per-tile exclusive scans + tile totals ------
__global__ void k_scan1() {
    __shared__ int s_ws[32], s_off[32];
    int t = threadIdx.x, w = t >> 5, lane = t & 31;
    int i = blockIdx.x * 1024 + t;
    int v = (i < N_NODES) ? g_deg[i] : 0;
    int incl = v;
#pragma unroll
    for (int o = 1; o < 32; o <<= 1) {
        int u = __shfl_up_sync(0xffffffffu, incl, o);
        if (lane >= o) incl += u;
    }
    if (lane == 31) s_ws[w] = incl;
    __syncthreads();
    if (w == 0) {
        int wv = s_ws[lane];
        int inc2 = wv;
#pragma unroll
        for (int o = 1; o < 32; o <<= 1) {
            int u = __shfl_up_sync(0xffffffffu, inc2, o);
            if (lane >= o) inc2 += u;
        }
        s_off[lane] = inc2 - wv;
        if (lane == 31) g_tsum[blockIdx.x] = inc2;
    }
    __syncthreads();
    if (i < N_NODES) g_rowptr[i] = s_off[w] + incl - v;  // tile-local exclusive
}

// ---------------- K: scan phase 2 — scan tile totals (1 block, 64 thr) ----------
__global__ void k_scan2() {
    __shared__ int s[64];
    int t = threadIdx.x;
    int v = (t < NTILES) ? g_tsum[t] : 0;
    s[t] = v;
    __syncthreads();
#pragma unroll
    for (int o = 1; o < 64; o <<= 1) {
        int add = (t >= o) ? s[t - o] : 0;
        __syncthreads();
        s[t] += add;
        __syncthreads();
    }
    if (t < NTILES) g_toff[t] = s[t] - v;
    if (t == NTILES - 1) g_rowptr[N_NODES] = s[t];
}

// ---------------- K: scan phase 3 — add tile offsets, init cursor ---------------
__global__ void k_scan3() {
    int i = blockIdx.x * 1024 + threadIdx.x;
    if (i < N_NODES) {
        int v = g_rowptr[i] + g_toff[blockIdx.x];
        g_rowptr[i] = v;
        g_cursor[i] = v;
    }
}

// ---------------- K: exp(leaky(alpha)) + light CSR scatter -----------------------
__global__ void k_alpha(const int* __restrict__ ei,
                        const float* __restrict__ eattr) {
    __shared__ float qs[48];
    if (threadIdx.x < 48) qs[threadIdx.x] = g_q[threadIdx.x];
    __syncthreads();
    int e = blockIdx.x * blockDim.x + threadIdx.x;
    if (e >= N_EDGES) return;
    int src = ei[e];
    int dst = ei[N_EDGES + e];
    const float4* ap = reinterpret_cast<const float4*>(eattr) + (size_t)e * 4;
    float4 a0 = ap[0], a1 = ap[1], a2 = ap[2], a3 = ap[3];
    float4 sd = *reinterpret_cast<const float4*>(g_sn + (size_t)dst * 8);
    float4 ss = *reinterpret_cast<const float4*>(g_sn + (size_t)src * 8 + 4);
    float base3[3] = {sd.x + ss.x, sd.y + ss.y, sd.z + ss.z};
    float w[3];
#pragma unroll
    for (int h = 0; h < 3; h++) {
        const float* q = qs + h * 16;
        float s = base3[h];
        s += a0.x * q[0]  + a0.y * q[1]  + a0.z * q[2]  + a0.w * q[3];
        s += a1.x * q[4]  + a1.y * q[5]  + a1.z * q[6]  + a1.w * q[7];
        s += a2.x * q[8]  + a2.y * q[9]  + a2.z * q[10] + a2.w * q[11];
        s += a3.x * q[12] + a3.y * q[13] + a3.z * q[14] + a3.w * q[15];
        s = (s >= 0.f) ? s : NEG_SLOPE * s;   // leaky relu
        w[h] = __expf(s);                     // shift-free softmax numerator
    }
    int pos = atomicAdd(&g_cursor[dst], 1);
    g_wsrc[pos] = make_float4(w[0], w[1], w[2], __int_as_float(src));
    g_eid[pos] = e;
}

// ---------------- K: per-node aggregation — ONE NODE PER BLOCK -------------------
// 96 threads: thread t owns channels (2t, 2t+1); head h = t>>5 (warp-uniform).
// Staging spread over all 96 threads for 4x gather MLP; SM-level overlap via
// ~21 concurrent small blocks instead of serial node loops.
#define CHUNK 32
__global__ void __launch_bounds__(96) k_aggr(const float* __restrict__ eattr,
                                             const float* __restrict__ We) {
    int t = threadIdx.x;
    int c0 = 2 * t;
    int h = t >> 5;

    unsigned long long Wp0[8], Wp1[8];
#pragma unroll
    for (int m = 0; m < 8; m++) {
        Wp0[m] = pk2(We[(2 * m) * HC + c0],     We[(2 * m + 1) * HC + c0]);
        Wp1[m] = pk2(We[(2 * m) * HC + c0 + 1], We[(2 * m + 1) * HC + c0 + 1]);
    }

    __shared__ float s_w[3 * CHUNK];
    __shared__ int   s_src[CHUNK];
    __shared__ __align__(16) float s_ea[CHUNK * 16];

    int i = blockIdx.x;
    int rs = g_rowptr[i], re = g_rowptr[i + 1];
    float z = 0.f;
    unsigned long long acc0 = 0ull, acc1 = 0ull;

    for (int base = rs; base < re; base += CHUNK) {
        int Cn = min(CHUNK, re - base);
        if (t < Cn) {
            float4 ws = g_wsrc[base + t];
            s_w[0 * CHUNK + t] = ws.x;
            s_w[1 * CHUNK + t] = ws.y;
            s_w[2 * CHUNK + t] = ws.z;
            s_src[t] = __float_as_int(ws.w);
        }
        // eattr gather spread across all 96 threads (4 float4 per edge)
        for (int u = t; u < Cn * 4; u += 96) {
            int edge = u >> 2, part = u & 3;
            int eid = g_eid[base + edge];
            reinterpret_cast<float4*>(s_ea)[u] =
                reinterpret_cast<const float4*>(eattr)[(size_t)eid * 4 + part];
        }
        __syncthreads();

        int srcc = s_src[0];
        __half2 xh = *reinterpret_cast<const __half2*>(
            g_xh + (size_t)srcc * HC + c0);
        for (int j = 0; j < Cn; j++) {
            __half2 xhn;
            if (j + 1 < Cn) {
                int srcn = s_src[j + 1];
                xhn = *reinterpret_cast<const __half2*>(
                    g_xh + (size_t)srcn * HC + c0);
            }
            float2 xj = __half22float2(xh);
            const ulonglong2* eap =
                reinterpret_cast<const ulonglong2*>(s_ea + j * 16);
            ulonglong2 p0 = eap[0], p1 = eap[1], p2 = eap[2], p3 = eap[3];
            unsigned long long e0 = 0ull, e1 = 0ull;
            fma2(e0, p0.x, Wp0[0]); fma2(e1, p0.x, Wp1[0]);
            fma2(e0, p0.y, Wp0[1]); fma2(e1, p0.y, Wp1[1]);
            fma2(e0, p1.x, Wp0[2]); fma2(e1, p1.x, Wp1[2]);
            fma2(e0, p1.y, Wp0[3]); fma2(e1, p1.y, Wp1[3]);
            fma2(e0, p2.x, Wp0[4]); fma2(e1, p2.x, Wp1[4]);
            fma2(e0, p2.y, Wp0[5]); fma2(e1, p2.y, Wp1[5]);
            fma2(e0, p3.x, Wp0[6]); fma2(e1, p3.x, Wp1[6]);
            fma2(e0, p3.y, Wp0[7]); fma2(e1, p3.y, Wp1[7]);
            float w = s_w[h * CHUNK + j];
            z += w;
            float wx0 = w * xj.x, wx1 = w * xj.y;
            fma2(acc0, e0, pk2(wx0, wx0));
            fma2(acc1, e1, pk2(wx1, wx1));
            xh = xhn;
        }
        __syncthreads();
    }
    float inv = 1.f / (z + 1e-16f);
    *reinterpret_cast<float2*>(g_aggr + (size_t)i * HC + c0) =
        make_float2(hsum2(acc0) * inv, hsum2(acc1) * inv);
}

// ---------------- K: out = aggr @ W_scale + bias ---------------------------------
__global__ void k_out(const float* __restrict__ Ws, const float* __restrict__ bias,
                      float* __restrict__ out) {
    __shared__ __align__(16) float aT[HC * 8];  // [k][n]
    int n0 = blockIdx.x * 8;
    int t = threadIdx.x;  // 0..63
    for (int i = t; i < 8 * HC; i += 64) {
        int n = i / HC, k = i - n * HC;
        aT[k * 8 + n] = g_aggr[(n0 + n) * HC + k];
    }
    __syncthreads();
    unsigned long long acc2[4];
#pragma unroll
    for (int p = 0; p < 4; p++) acc2[p] = 0ull;
#pragma unroll 4
    for (int k = 0; k < HC; k++) {
        unsigned long long wv2 = pk2(Ws[k * 64 + t], Ws[k * 64 + t]);
        const ulonglong2* ar =
            reinterpret_cast<const ulonglong2*>(aT + k * 8);
        ulonglong2 v01 = ar[0], v23 = ar[1];
        fma2(acc2[0], v01.x, wv2); fma2(acc2[1], v01.y, wv2);
        fma2(acc2[2], v23.x, wv2); fma2(acc2[3], v23.y, wv2);
    }
    float acc[8];
#pragma unroll
    for (int p = 0; p < 4; p++) unpk2(acc[2 * p], acc[2 * p + 1], acc2[p]);
    float b = bias[t];
#pragma unroll
    for (int n = 0; n < 8; n++) out[(n0 + n) * 64 + t] = acc[n] + b;
}

// ---------------- launch ----------------------------------------------------------
extern "C" void kernel_launch(void* const* d_in, const int* in_sizes, int n_in,
                              void* d_out, int out_size) {
    const float* x     = (const float*)d_in[0];
    const int*   ei    = (const int*)d_in[1];
    const float* eattr = (const float*)d_in[2];
    const float* Wn    = (const float*)d_in[3];
    const float* We    = (const float*)d_in[4];
    const float* att   = (const float*)d_in[5];
    const float* Ws    = (const float*)d_in[6];
    const float* bias  = (const float*)d_in[7];
    float*       out   = (float*)d_out;

    k_zero<<<(N_NODES + 255) / 256, 256>>>();
    k_deg<<<(N_EDGES + 255) / 256, 256>>>(ei);
    k_fold<<<1, 448>>>(Wn, We, att);
    k_projs<<<N_NODES / 8, 96>>>(x, Wn);
    k_scan1<<<NTILES, 1024>>>();
    k_scan2<<<1, 64>>>();
    k_scan3<<<NTILES, 1024>>>();
    k_alpha<<<(N_EDGES + 255) / 256, 256>>>(ei, eattr);
    k_aggr<<<N_NODES, 96>>>(eattr, We);
    k_out<<<N_NODES / 8, 64>>>(Ws, bias, out);
}

// round 9
// speedup vs baseline: 1.0605x; 1.0038x over previous
#include <cuda_runtime.h>
#include <cuda_fp16.h>

#define N_NODES 50000
#define N_EDGES 800000
#define HEADS 3
#define HC 192
#define NEG_SLOPE 0.2f
#define NTILES 49   // ceil(50000/1024)

// ---------------- scratch ------------------------------------------------------
__device__ __half  g_xh[N_NODES * HC];       // x @ W_node (fp16, message path)
__device__ float   g_sn[N_NODES * 8];        // [0..2]=s0(h), [4..6]=s2(h)
__device__ float   g_q[64];                  // folded edge-att vector (48 used)
__device__ float   g_v[6 * 64];              // folded node-att vectors v0/v2
__device__ int2    g_se[N_EDGES];            // CSR: (src, eid)
__device__ int     g_deg[N_NODES];
__device__ int     g_rowptr[N_NODES + 1];
__device__ int     g_cursor[N_NODES];
__device__ int     g_tsum[64], g_toff[64];
__device__ float   g_aggr[N_NODES * HC];

// ---------------- f32x2 helpers -------------------------------------------------
__device__ __forceinline__ unsigned long long pk2(float lo, float hi) {
    unsigned long long r;
    asm("mov.b64 %0, {%1,%2};" : "=l"(r) : "f"(lo), "f"(hi));
    return r;
}
__device__ __forceinline__ void fma2(unsigned long long& d,
                                     unsigned long long a,
                                     unsigned long long b) {
    asm("fma.rn.f32x2 %0, %1, %2, %0;" : "+l"(d) : "l"(a), "l"(b));
}
__device__ __forceinline__ void unpk2(float& lo, float& hi, unsigned long long v) {
    asm("mov.b64 {%0,%1}, %2;" : "=f"(lo), "=f"(hi) : "l"(v));
}
__device__ __forceinline__ float hsum2(unsigned long long v) {
    float lo, hi; unpk2(lo, hi, v); return lo + hi;
}

// ---------------- K: zero degree histogram --------------------------------------
__global__ void k_zero() {
    int i = blockIdx.x * blockDim.x + threadIdx.x;
    if (i < N_NODES) g_deg[i] = 0;
}

// ---------------- K: degree histogram -------------------------------------------
__global__ void k_deg(const int* __restrict__ ei) {
    int e = blockIdx.x * blockDim.x + threadIdx.x;
    if (e < N_EDGES) atomicAdd(&g_deg[ei[N_EDGES + e]], 1);
}

// ---------------- K: fold attention vectors -------------------------------------
__global__ void k_fold(const float* __restrict__ Wn, const float* __restrict__ We,
                       const float* __restrict__ att) {
    int t = threadIdx.x;
    if (t < 48) {
        int h = t >> 4, k = t & 15;
        float s = 0.f;
        const float* wr = We + k * HC + h * 64;
        const float* ar = att + h * HC + 64;
#pragma unroll 8
        for (int c = 0; c < 64; c++) s += wr[c] * ar[c];
        g_q[t] = s;
    } else if (t < 48 + 384) {
        int o2 = t - 48;
        int o = o2 >> 6, k = o2 & 63;
        int type = (o >= 3), h = (o >= 3) ? o - 3 : o;
        float s = 0.f;
        const float* wr = Wn + k * HC + h * 64;
        const float* ar = att + h * HC + type * 128;
#pragma unroll 8
        for (int c = 0; c < 64; c++) s += wr[c] * ar[c];
        g_v[o * 64 + k] = s;
    }
}

// ---------------- K: x_proj = x @ W_node (fp16 out) + shuffle-free s0/s2 --------
__global__ void k_projs(const float* __restrict__ x, const float* __restrict__ Wn) {
    __shared__ __align__(16) float xT[64 * 8];  // [k][n]
    __shared__ float s_v[6 * 65];               // padded folded vectors
    int n0 = blockIdx.x * 8;
    int t = threadIdx.x;                 // 0..95
    int ch0 = t, ch1 = t + 96;
    for (int i = t; i < 8 * 64; i += 96) {
        int n = i >> 6, k = i & 63;
        xT[k * 8 + n] = x[(n0 + n) * 64 + k];
    }
    for (int i = t; i < 384; i += 96) {
        int o = i >> 6, k = i & 63;
        s_v[o * 65 + k] = g_v[i];
    }
    __syncthreads();
    unsigned long long accA2[4], accB2[4];
#pragma unroll
    for (int p = 0; p < 4; p++) { accA2[p] = 0ull; accB2[p] = 0ull; }
#pragma unroll 4
    for (int k = 0; k < 64; k++) {
        float wa = Wn[k * HC + ch0];
        float wb = Wn[k * HC + ch1];
        unsigned long long wa2 = pk2(wa, wa), wb2 = pk2(wb, wb);
        const ulonglong2* xr = reinterpret_cast<const ulonglong2*>(xT + k * 8);
        ulonglong2 x01 = xr[0], x23 = xr[1];
        fma2(accA2[0], x01.x, wa2); fma2(accA2[1], x01.y, wa2);
        fma2(accA2[2], x23.x, wa2); fma2(accA2[3], x23.y, wa2);
        fma2(accB2[0], x01.x, wb2); fma2(accB2[1], x01.y, wb2);
        fma2(accB2[2], x23.x, wb2); fma2(accB2[3], x23.y, wb2);
    }
    float accA[8], accB[8];
#pragma unroll
    for (int p = 0; p < 4; p++) {
        unpk2(accA[2 * p], accA[2 * p + 1], accA2[p]);
        unpk2(accB[2 * p], accB[2 * p + 1], accB2[p]);
    }
#pragma unroll
    for (int n = 0; n < 8; n++) {
        g_xh[(n0 + n) * HC + ch0] = __float2half(accA[n]);
        g_xh[(n0 + n) * HC + ch1] = __float2half(accB[n]);
    }

    // shuffle-free s0/s2: 48 dots of length 64 from the staged xT tile
    if (t < 48) {
        int n = t & 7, o = t >> 3;          // o = type*3 + h
        int type = (o >= 3), h = (o >= 3) ? o - 3 : o;
        const float* vv = s_v + o * 65;
        float s = 0.f;
#pragma unroll 8
        for (int k = 0; k < 64; k++) s += xT[k * 8 + n] * vv[k];
        g_sn[(n0 + n) * 8 + type * 4 + h] = s;
    }
}

// ---------------- K: scan phase 1 ------------------------------------------------
__global__ void k_scan1() {
    __shared__ int s_ws[32], s_off[32];
    int t = threadIdx.x, w = t >> 5, lane = t & 31;
    int i = blockIdx.x * 1024 + t;
    int v = (i < N_NODES) ? g_deg[i] : 0;
    int incl = v;
#pragma unroll
    for (int o = 1; o < 32; o <<= 1) {
        int u = __shfl_up_sync(0xffffffffu, incl, o);
        if (lane >= o) incl += u;
    }
    if (lane == 31) s_ws[w] = incl;
    __syncthreads();
    if (w == 0) {
        int wv = s_ws[lane];
        int inc2 = wv;
#pragma unroll
        for (int o = 1; o < 32; o <<= 1) {
            int u = __shfl_up_sync(0xffffffffu, inc2, o);
            if (lane >= o) inc2 += u;
        }
        s_off[lane] = inc2 - wv;
        if (lane == 31) g_tsum[blockIdx.x] = inc2;
    }
    __syncthreads();
    if (i < N_NODES) g_rowptr[i] = s_off[w] + incl - v;
}

// ---------------- K: scan phase 2 -------------------------------------------------
__global__ void k_scan2() {
    __shared__ int s[64];
    int t = threadIdx.x;
    int v = (t < NTILES) ? g_tsum[t] : 0;
    s[t] = v;
    __syncthreads();
#pragma unroll
    for (int o = 1; o < 64; o <<= 1) {
        int add = (t >= o) ? s[t - o] : 0;
        __syncthreads();
        s[t] += add;
        __syncthreads();
    }
    if (t < NTILES) g_toff[t] = s[t] - v;
    if (t == NTILES - 1) g_rowptr[N_NODES] = s[t];
}

// ---------------- K: scan phase 3 -------------------------------------------------
__global__ void k_scan3() {
    int i = blockIdx.x * 1024 + threadIdx.x;
    if (i < N_NODES) {
        int v = g_rowptr[i] + g_toff[blockIdx.x];
        g_rowptr[i] = v;
        g_cursor[i] = v;
    }
}

// ---------------- K: light CSR scatter of (src, eid) ------------------------------
__global__ void k_scatter(const int* __restrict__ ei) {
    int e = blockIdx.x * blockDim.x + threadIdx.x;
    if (e >= N_EDGES) return;
    int src = ei[e];
    int dst = ei[N_EDGES + e];
    int pos = atomicAdd(&g_cursor[dst], 1);
    g_se[pos] = make_int2(src, e);
}

// ---------------- K: per-node aggregation with in-block alpha ---------------------
// One node per block. 96 threads: thread t owns channels (2t,2t+1); h = t>>5.
// Alpha phase: thread (h = warp, ae = lane) computes edge ae's head-h logit.
#define CHUNK 32
__global__ void __launch_bounds__(96) k_aggr(const float* __restrict__ eattr,
                                             const float* __restrict__ We) {
    int t = threadIdx.x;
    int c0 = 2 * t;
    int h = t >> 5;
    int ae = t & 31;

    unsigned long long Wp0[8], Wp1[8];
#pragma unroll
    for (int m = 0; m < 8; m++) {
        Wp0[m] = pk2(We[(2 * m) * HC + c0],     We[(2 * m + 1) * HC + c0]);
        Wp1[m] = pk2(We[(2 * m) * HC + c0 + 1], We[(2 * m + 1) * HC + c0 + 1]);
    }

    __shared__ float qs[48];
    __shared__ float s_w[3 * CHUNK];
    __shared__ int   s_src[CHUNK];
    __shared__ __align__(16) float4 s_sn2[CHUNK];
    __shared__ __align__(16) float  s_ea[CHUNK * 16];
    if (t < 48) qs[t] = g_q[t];

    int i = blockIdx.x;
    int rs = g_rowptr[i], re = g_rowptr[i + 1];
    float sb = g_sn[(size_t)i * 8 + h];      // dst s0 for my head (warp-uniform)
    float z = 0.f;
    unsigned long long acc0 = 0ull, acc1 = 0ull;

    for (int base = rs; base < re; base += CHUNK) {
        int Cn = min(CHUNK, re - base);
        if (t < Cn) {
            int2 se = g_se[base + t];
            s_src[t] = se.x;
            s_sn2[t] = *reinterpret_cast<const float4*>(g_sn + (size_t)se.x * 8 + 4);
        }
        // eattr gather spread across all 96 threads (4 float4 per edge)
        for (int u = t; u < Cn * 4; u += 96) {
            int edge = u >> 2, part = u & 3;
            int eid = g_se[base + edge].y;
            reinterpret_cast<float4*>(s_ea)[u] =
                reinterpret_cast<const float4*>(eattr)[(size_t)eid * 4 + part];
        }
        __syncthreads();

        // alpha for (edge ae, head h): 16-dot + leaky + exp
        if (ae < Cn) {
            const float* q = qs + h * 16;
            const float4* er = reinterpret_cast<const float4*>(s_ea + ae * 16);
            float4 b0 = er[0], b1 = er[1], b2 = er[2], b3 = er[3];
            float s = sb + reinterpret_cast<const float*>(&s_sn2[ae])[h];
            s += b0.x * q[0]  + b0.y * q[1]  + b0.z * q[2]  + b0.w * q[3];
            s += b1.x * q[4]  + b1.y * q[5]  + b1.z * q[6]  + b1.w * q[7];
            s += b2.x * q[8]  + b2.y * q[9]  + b2.z * q[10] + b2.w * q[11];
            s += b3.x * q[12] + b3.y * q[13] + b3.z * q[14] + b3.w * q[15];
            s = (s >= 0.f) ? s : NEG_SLOPE * s;
            s_w[h * CHUNK + ae] = __expf(s);
        }
        __syncwarp();   // s_w: writer lane == reader warp

        int srcc = s_src[0];
        __half2 xh = *reinterpret_cast<const __half2*>(
            g_xh + (size_t)srcc * HC + c0);
        for (int j = 0; j < Cn; j++) {
            __half2 xhn;
            if (j + 1 < Cn) {
                int srcn = s_src[j + 1];
                xhn = *reinterpret_cast<const __half2*>(
                    g_xh + (size_t)srcn * HC + c0);
            }
            float2 xj = __half22float2(xh);
            const ulonglong2* eap =
                reinterpret_cast<const ulonglong2*>(s_ea + j * 16);
            ulonglong2 p0 = eap[0], p1 = eap[1], p2 = eap[2], p3 = eap[3];
            unsigned long long e0 = 0ull, e1 = 0ull;
            fma2(e0, p0.x, Wp0[0]); fma2(e1, p0.x, Wp1[0]);
            fma2(e0, p0.y, Wp0[1]); fma2(e1, p0.y, Wp1[1]);
            fma2(e0, p1.x, Wp0[2]); fma2(e1, p1.x, Wp1[2]);
            fma2(e0, p1.y, Wp0[3]); fma2(e1, p1.y, Wp1[3]);
            fma2(e0, p2.x, Wp0[4]); fma2(e1, p2.x, Wp1[4]);
            fma2(e0, p2.y, Wp0[5]); fma2(e1, p2.y, Wp1[5]);
            fma2(e0, p3.x, Wp0[6]); fma2(e1, p3.x, Wp1[6]);
            fma2(e0, p3.y, Wp0[7]); fma2(e1, p3.y, Wp1[7]);
            float w = s_w[h * CHUNK + j];
            z += w;
            float wx0 = w * xj.x, wx1 = w * xj.y;
            fma2(acc0, e0, pk2(wx0, wx0));
            fma2(acc1, e1, pk2(wx1, wx1));
            xh = xhn;
        }
        __syncthreads();
    }
    float inv = 1.f / (z + 1e-16f);
    *reinterpret_cast<float2*>(g_aggr + (size_t)i * HC + c0) =
        make_float2(hsum2(acc0) * inv, hsum2(acc1) * inv);
}

// ---------------- K: out = aggr @ W_scale + bias ---------------------------------
__global__ void k_out(const float* __restrict__ Ws, const float* __restrict__ bias,
                      float* __restrict__ out) {
    __shared__ __align__(16) float aT[HC * 8];  // [k][n]
    int n0 = blockIdx.x * 8;
    int t = threadIdx.x;  // 0..63
    for (int i = t; i < 8 * HC; i += 64) {
        int n = i / HC, k = i - n * HC;
        aT[k * 8 + n] = g_aggr[(n0 + n) * HC + k];
    }
    __syncthreads();
    unsigned long long acc2[4];
#pragma unroll
    for (int p = 0; p < 4; p++) acc2[p] = 0ull;
#pragma unroll 4
    for (int k = 0; k < HC; k++) {
        unsigned long long wv2 = pk2(Ws[k * 64 + t], Ws[k * 64 + t]);
        const ulonglong2* ar =
            reinterpret_cast<const ulonglong2*>(aT + k * 8);
        ulonglong2 v01 = ar[0], v23 = ar[1];
        fma2(acc2[0], v01.x, wv2); fma2(acc2[1], v01.y, wv2);
        fma2(acc2[2], v23.x, wv2); fma2(acc2[3], v23.y, wv2);
    }
    float acc[8];
#pragma unroll
    for (int p = 0; p < 4; p++) unpk2(acc[2 * p], acc[2 * p + 1], acc2[p]);
    float b = bias[t];
#pragma unroll
    for (int n = 0; n < 8; n++) out[(n0 + n) * 64 + t] = acc[n] + b;
}

// ---------------- launch ----------------------------------------------------------
extern "C" void kernel_launch(void* const* d_in, const int* in_sizes, int n_in,
                              void* d_out, int out_size) {
    const float* x     = (const float*)d_in[0];
    const int*   ei    = (const int*)d_in[1];
    const float* eattr = (const float*)d_in[2];
    const float* Wn    = (const float*)d_in[3];
    const float* We    = (const float*)d_in[4];
    const float* att   = (const float*)d_in[5];
    const float* Ws    = (const float*)d_in[6];
    const float* bias  = (const float*)d_in[7];
    float*       out   = (float*)d_out;

    k_zero<<<(N_NODES + 255) / 256, 256>>>();
    k_deg<<<(N_EDGES + 255) / 256, 256>>>(ei);
    k_fold<<<1, 448>>>(Wn, We, att);
    k_projs<<<N_NODES / 8, 96>>>(x, Wn);
    k_scan1<<<NTILES, 1024>>>();
    k_scan2<<<1, 64>>>();
    k_scan3<<<NTILES, 1024>>>();
    k_scatter<<<(N_EDGES + 255) / 256, 256>>>(ei);
    k_aggr<<<N_NODES, 96>>>(eattr, We);
    k_out<<<N_NODES / 8, 64>>>(Ws, bias, out);
}